// round 4
// baseline (speedup 1.0000x reference)
#include <cuda_runtime.h>
#include <cstdint>

// OverlapPatchEmbed: extract overlapping 16x16 patches with stride 8 from
// x (64, 3, 224, 224) fp32 -> out (64, 729, 3, 256) fp32.
//
// R2 design (resubmit #2 after broker timeouts): latency-bound fix. Each
// thread handles 4 independent float4 copies at stride Q (quarter of the
// output), giving MLP=4 per thread so the L1tex queue stays full. Warp
// stores remain perfectly coalesced within each quarter. Output stores use
// __stcs (streaming / evict-first) so the 143MB write-once output doesn't
// evict the 38.5MB input (which is read ~4x via L2 residency).

static constexpr int B  = 64;
static constexpr int C  = 3;
static constexpr int H  = 224;
static constexpr int W  = 224;
static constexpr int P  = 16;   // patch_size
static constexpr int S  = 8;    // stride = patch_size - overlap
static constexpr int N  = 27;   // patches per dim
static constexpr int OUT_ELEMS = B * N * N * C * P * P;  // 35,831,808
static constexpr int OUT_VEC4  = OUT_ELEMS / 4;          // 8,957,952
static constexpr int Q         = OUT_VEC4 / 4;           // 2,239,488 (exact)

__device__ __forceinline__ const float4* src_addr(const float* __restrict__ x, int i)
{
    // Decompose output float4 index:
    // layout (b, py, px, c, ky, kx4) with kx4 in [0,4) selecting 4 floats.
    int kx4 = i & 3;
    int t   = i >> 2;
    int ky  = t & 15;
    t >>= 4;
    int c   = t % C;
    t /= C;
    int px  = t % N;
    t /= N;
    int py  = t % N;
    int b   = t / N;

    int row = py * S + ky;
    int col = px * S + kx4 * 4;

    return reinterpret_cast<const float4*>(
        x + (((int64_t)b * C + c) * H + row) * W + col);
}

__global__ __launch_bounds__(256)
void overlap_patch_kernel(const float* __restrict__ x,
                          float* __restrict__ out)
{
    int i0 = blockIdx.x * blockDim.x + threadIdx.x;   // in [0, Q)
    if (i0 >= Q) return;

    float4* o = reinterpret_cast<float4*>(out);

    // 4 independent gather->store pairs; compiler front-batches the LDGs.
    const float4* s0 = src_addr(x, i0);
    const float4* s1 = src_addr(x, i0 + Q);
    const float4* s2 = src_addr(x, i0 + 2 * Q);
    const float4* s3 = src_addr(x, i0 + 3 * Q);

    float4 v0 = __ldg(s0);
    float4 v1 = __ldg(s1);
    float4 v2 = __ldg(s2);
    float4 v3 = __ldg(s3);

    __stcs(&o[i0],         v0);
    __stcs(&o[i0 + Q],     v1);
    __stcs(&o[i0 + 2 * Q], v2);
    __stcs(&o[i0 + 3 * Q], v3);
}

extern "C" void kernel_launch(void* const* d_in, const int* in_sizes, int n_in,
                              void* d_out, int out_size)
{
    const float* x = (const float*)d_in[0];
    float* out = (float*)d_out;

    int threads = 256;
    int blocks = (Q + threads - 1) / threads;   // 8748 blocks
    overlap_patch_kernel<<<blocks, threads>>>(x, out);
}

// round 5
// speedup vs baseline: 1.5137x; 1.5137x over previous
#include <cuda_runtime.h>
#include <cstdint>

// OverlapPatchEmbed: x (64,3,224,224) fp32 -> out (64,729,3,256) fp32.
// 16x16 patches, stride 8, 27x27 patches per image.
//
// R4: shared-memory staged (transpose-style). CTA = one (b, py) band.
//  - Load phase: 3 contiguous gmem chunks (16 rows x 224 floats per channel,
//    43KB total) -> smem with pitch 240 floats. Fully coalesced LDG.128.
//  - Store phase: emit 27 patches x 768 floats = 81KB as ONE contiguous
//    gmem range. Fully coalesced STG.128 (__stcs, streaming).
//  - Smem gather (the scattered part) is conflict-free: bank group of a
//    float4 read = (4*ky + kx4) mod 8, distinct within each quarter-warp.
// 192 threads: 2688 load float4 (14/thread) and 5184 store float4
// (27/thread) divide exactly.

static constexpr int B  = 64;
static constexpr int C  = 3;
static constexpr int H  = 224;
static constexpr int W  = 224;
static constexpr int P  = 16;     // patch size
static constexpr int S  = 8;      // stride
static constexpr int N  = 27;     // patches per dim

static constexpr int W_F4       = W / 4;            // 56 float4 per row
static constexpr int PITCH_F4   = 60;               // 240-float pitch (bank-conflict-free)
static constexpr int CH_F4      = P * PITCH_F4;     // 960 float4 per channel slab
static constexpr int SMEM_F4    = C * CH_F4;        // 2880 float4 = 46080 B

static constexpr int THREADS    = 192;
static constexpr int LOAD_F4    = C * P * W_F4;     // 2688 -> 14 iters
static constexpr int STORE_F4   = N * C * P * P / 4; // 5184 -> 27 iters
static constexpr int LOAD_ITERS  = LOAD_F4 / THREADS;   // 14
static constexpr int STORE_ITERS = STORE_F4 / THREADS;  // 27

__global__ __launch_bounds__(THREADS)
void overlap_patch_kernel(const float4* __restrict__ x,
                          float4* __restrict__ out)
{
    __shared__ float4 sm[SMEM_F4];   // 45 KB static

    const int tid = threadIdx.x;
    const int b   = blockIdx.x / N;
    const int py  = blockIdx.x - b * N;

    // ---- Load phase: 3 contiguous chunks of 16 rows x 224 floats ----
    // gmem float4 base for (b, c): ((b*3 + c)*224 + py*8) * 56
    #pragma unroll
    for (int k = 0; k < LOAD_ITERS; k++) {
        int g      = tid + k * THREADS;          // [0, 2688)
        int c      = g / (P * W_F4);             // /896
        int within = g - c * (P * W_F4);         // [0, 896)
        int row    = within / W_F4;              // /56
        int col4   = within - row * W_F4;

        int64_t gsrc = ((int64_t)(b * C + c) * H + (py * S + row)) * W_F4 + col4;
        sm[c * CH_F4 + row * PITCH_F4 + col4] = __ldg(&x[gsrc]);
    }

    __syncthreads();

    // ---- Store phase: 27*768 = 20736 consecutive output floats ----
    // out float4 base = (b*729 + py*27) * 192
    const int64_t obase = (int64_t)(b * (N * N) + py * N) * (C * P * P / 4);

    #pragma unroll
    for (int k = 0; k < STORE_ITERS; k++) {
        int j   = tid + k * THREADS;             // [0, 5184)
        int kx4 = j & 3;                         // float4 within 16-wide row
        int ky  = (j >> 2) & 15;                 // row within patch
        int t   = j >> 6;                        // (px, c)
        int c   = t % C;
        int px  = t / C;

        // smem addr: channel slab + patch row + horizontal offset px*8 floats
        float4 v = sm[c * CH_F4 + ky * PITCH_F4 + px * 2 + kx4];
        __stcs(&out[obase + j], v);
    }
}

extern "C" void kernel_launch(void* const* d_in, const int* in_sizes, int n_in,
                              void* d_out, int out_size)
{
    const float4* x = (const float4*)d_in[0];
    float4* out = (float4*)d_out;

    overlap_patch_kernel<<<B * N, THREADS>>>(x, out);   // 1728 CTAs
}